// round 1
// baseline (speedup 1.0000x reference)
#include <cuda_runtime.h>
#include <cuda_bf16.h>

// Problem constants (fixed by reference: x [64,1,512,512] f32, kernel [49] f32)
#define LW      7
#define PAD     3
#define A_W     0.3f
#define B_W     0.7f
#define TILE    32
#define RY      4          // rows per thread
#define BXT     32         // block dim x
#define BYT     8          // block dim y (BYT*RY = TILE)
#define SH_W    (TILE + 6) // 38
#define SH_STR  40         // shared row stride (floats)
#define IMG     512
#define NPIX    (IMG * IMG)

__device__ double g_sum;
__device__ float  g_inv;

// Fallback scratch in case d_out only holds the first output (hedge; normally unused)
__device__ float g_scr_avg[64 * NPIX];
__device__ float g_scr_diff[64 * NPIX];

__global__ void zero_kernel() { g_sum = 0.0; }

__global__ void norm_kernel() { g_inv = rsqrtf((float)g_sum); }

__global__ __launch_bounds__(BXT * BYT)
void stencil_kernel(const float* __restrict__ x, const float* __restrict__ w,
                    float* __restrict__ avg_out, float* __restrict__ diff_out)
{
    __shared__ float tile[SH_W][SH_STR];
    __shared__ float sw[49];
    __shared__ float red[BYT];

    const int tx  = threadIdx.x;
    const int ty  = threadIdx.y;
    const int tid = ty * BXT + tx;
    const int bx  = blockIdx.x * TILE;
    const int by  = blockIdx.y * TILE;
    const int b   = blockIdx.z;
    const float* xb = x + (size_t)b * NPIX;

    if (tid < 49) sw[tid] = w[tid];

    // Load padded tile: rows [by-3, by+35), cols [bx-3, bx+35), zero OOB
    #pragma unroll
    for (int idx = tid; idx < SH_W * SH_W; idx += BXT * BYT) {
        int r  = idx / SH_W;
        int c  = idx - r * SH_W;
        int gy = by + r - PAD;
        int gx = bx + c - PAD;
        float v = 0.f;
        if ((unsigned)gy < IMG && (unsigned)gx < IMG) v = xb[gy * IMG + gx];
        tile[r][c] = v;
    }
    __syncthreads();

    const int r0 = ty * RY;  // local output row base for this thread
    float xc[RY], mean[RY], diff[RY];
    #pragma unroll
    for (int r = 0; r < RY; ++r) {
        xc[r]   = tile[r0 + r + PAD][tx + PAD];
        mean[r] = 0.f;
        diff[r] = 0.f;
    }

    // Sweep the RY+6 shared rows this thread touches; rowsum is computed once
    // per row (separable box-sum); the 49-tap relu/fma chain is per tap.
    #pragma unroll
    for (int k = 0; k < RY + 6; ++k) {
        float v[7];
        #pragma unroll
        for (int j = 0; j < 7; ++j) v[j] = tile[r0 + k][tx + j];
        float rowsum = ((v[0] + v[1]) + (v[2] + v[3])) + ((v[4] + v[5]) + v[6]);
        #pragma unroll
        for (int r = 0; r < RY; ++r) {
            const int i = k - r;   // tap row index for output row r
            if (0 <= i && i < 7) {
                mean[r] += rowsum;
                #pragma unroll
                for (int j = 0; j < 7; ++j) {
                    float d = v[j] - xc[r];
                    diff[r] = fmaf(sw[i * 7 + j], fmaxf(d, 0.f), diff[r]);
                }
            }
        }
    }

    // Epilogue: write avg/diff, accumulate ||mask_pre||^2 locally
    float local = 0.f;
    #pragma unroll
    for (int r = 0; r < RY; ++r) {
        float a = __expf(mean[r] * (-1.f / 49.f));
        size_t o = (size_t)b * NPIX + (size_t)(by + r0 + r) * IMG + (bx + tx);
        avg_out[o]  = a;
        diff_out[o] = diff[r];
        float m = A_W * a + B_W * diff[r];
        local += m * m;
    }

    // Block reduction -> single double atomic per block
    #pragma unroll
    for (int s = 16; s > 0; s >>= 1)
        local += __shfl_down_sync(0xffffffffu, local, s);
    const int lane = tid & 31, warp = tid >> 5;
    if (lane == 0) red[warp] = local;
    __syncthreads();
    if (warp == 0) {
        float v2 = (lane < BYT) ? red[lane] : 0.f;
        #pragma unroll
        for (int s = 4; s > 0; s >>= 1)
            v2 += __shfl_down_sync(0xffffffffu, v2, s);
        if (lane == 0) atomicAdd(&g_sum, (double)v2);
    }
}

__global__ __launch_bounds__(256)
void threshold_kernel(const float* __restrict__ x,
                      const float* __restrict__ avg_in,
                      const float* __restrict__ diff_in,
                      float* __restrict__ out, int n4)
{
    int i = blockIdx.x * blockDim.x + threadIdx.x;
    if (i >= n4) return;
    const float inv = g_inv;
    float4 xv = ((const float4*)x)[i];
    float4 av = ((const float4*)avg_in)[i];
    float4 dv = ((const float4*)diff_in)[i];
    float4 o;
    o.x = xv.x > (A_W * av.x + B_W * dv.x) * inv ? xv.x : 0.f;
    o.y = xv.y > (A_W * av.y + B_W * dv.y) * inv ? xv.y : 0.f;
    o.z = xv.z > (A_W * av.z + B_W * dv.z) * inv ? xv.z : 0.f;
    o.w = xv.w > (A_W * av.w + B_W * dv.w) * inv ? xv.w : 0.f;
    ((float4*)out)[i] = o;
}

extern "C" void kernel_launch(void* const* d_in, const int* in_sizes, int n_in,
                              void* d_out, int out_size)
{
    const float* x = (const float*)d_in[0];
    const float* w = (const float*)d_in[1];
    float* out = (float*)d_out;

    const int N     = in_sizes[0];        // 64*512*512
    const int batch = N / NPIX;           // 64

    // Outputs are the flattened tuple (out, average_term, differential_term).
    float* avg_ptr;
    float* diff_ptr;
    if (out_size >= 3 * N) {
        avg_ptr  = out + N;
        diff_ptr = out + 2 * N;
    } else {
        // hedge: tuple not concatenated -> use device-global scratch
        void* pa = nullptr; void* pd = nullptr;
        cudaGetSymbolAddress(&pa, g_scr_avg);
        cudaGetSymbolAddress(&pd, g_scr_diff);
        avg_ptr  = (float*)pa;
        diff_ptr = (float*)pd;
    }

    zero_kernel<<<1, 1>>>();

    dim3 grid(IMG / TILE, IMG / TILE, batch);
    dim3 block(BXT, BYT);
    stencil_kernel<<<grid, block>>>(x, w, avg_ptr, diff_ptr);

    norm_kernel<<<1, 1>>>();

    const int n4 = N / 4;
    threshold_kernel<<<(n4 + 255) / 256, 256>>>(x, avg_ptr, diff_ptr, out, n4);
}

// round 2
// speedup vs baseline: 1.0634x; 1.0634x over previous
#include <cuda_runtime.h>

#define IMG    512
#define NPIX   (IMG * IMG)
#define A_W    0.3f
#define B_W    0.7f

#define TXD    16
#define TYD    16
#define RY     2            // output rows per thread
#define CPT    4            // output cols per thread (2 packed pairs)
#define TILE_W 64           // TXD * CPT
#define TILE_H 32           // TYD * RY
#define SH_H   38           // TILE_H + 6
#define SH_W   70           // TILE_W + 6
#define S_STR  72           // shared row stride (floats), even for LDS.64 alignment
#define ABSM   0x7fffffff7fffffffULL

typedef unsigned long long ull;

__device__ double g_sum;
__device__ float  g_inv;
__device__ float  g_mask[64 * NPIX];   // pre-normalization mask scratch
// hedge if d_out only holds the first output (verified unused in round 1)
__device__ float  g_scr_a[64 * NPIX];
__device__ float  g_scr_d[64 * NPIX];

__device__ __forceinline__ ull f2add(ull a, ull b) {
    ull r; asm("add.rn.f32x2 %0, %1, %2;" : "=l"(r) : "l"(a), "l"(b)); return r;
}
__device__ __forceinline__ ull f2fma(ull a, ull b, ull c) {
    ull r; asm("fma.rn.f32x2 %0, %1, %2, %3;" : "=l"(r) : "l"(a), "l"(b), "l"(c)); return r;
}
__device__ __forceinline__ ull fpack(float lo, float hi) {
    ull r; asm("mov.b64 %0, {%1, %2};" : "=l"(r) : "f"(lo), "f"(hi)); return r;
}
__device__ __forceinline__ void f2unpack(ull a, float& lo, float& hi) {
    asm("mov.b64 {%0, %1}, %2;" : "=f"(lo), "=f"(hi) : "l"(a));
}

__global__ void zero_kernel() { g_sum = 0.0; }
__global__ void norm_kernel() { g_inv = rsqrtf((float)g_sum); }

__global__ __launch_bounds__(TXD * TYD)
void stencil_kernel(const float* __restrict__ x, const float* __restrict__ w,
                    float* __restrict__ avg_out, float* __restrict__ diff_out)
{
    __shared__ __align__(16) float tile[SH_H * S_STR];
    __shared__ ull   sw2[49];
    __shared__ float red[8];

    const int tx  = threadIdx.x;
    const int ty  = threadIdx.y;
    const int tid = ty * TXD + tx;
    const int bx  = blockIdx.x * TILE_W;
    const int by  = blockIdx.y * TILE_H;
    const int b   = blockIdx.z;
    const float* xb = x + (size_t)b * NPIX;

    if (tid < 49) { float h = 0.5f * w[tid]; sw2[tid] = fpack(h, h); }

    // Fill padded tile with row-parity bank swizzle: column c stored at c ^ (row & 2)
    for (int idx = tid; idx < SH_H * SH_W; idx += TXD * TYD) {
        int r  = idx / SH_W;
        int c  = idx - r * SH_W;
        int gy = by + r - 3;
        int gx = bx + c - 3;
        float v = 0.f;
        if ((unsigned)gy < IMG && (unsigned)gx < IMG) v = __ldg(&xb[gy * IMG + gx]);
        tile[r * S_STR + (c ^ (r & 2))] = v;
    }
    __syncthreads();

    const int c0 = tx * CPT;   // tile col of v[0] (= output col in padded coords)
    const int r0 = ty * RY;

    // Negated packed centers per output row (center = tile[row+3][col+3])
    ull nxc[RY][2];
    #pragma unroll
    for (int r = 0; r < RY; ++r) {
        int row = r0 + r + 3, sb = row * S_STR, sz = row & 2;
        float x0 = tile[sb + ((c0 + 3) ^ sz)];
        float x1 = tile[sb + ((c0 + 4) ^ sz)];
        float x2 = tile[sb + ((c0 + 5) ^ sz)];
        float x3 = tile[sb + ((c0 + 6) ^ sz)];
        nxc[r][0] = fpack(-x0, -x1);
        nxc[r][1] = fpack(-x2, -x3);
    }

    ull mean[RY][2] = {}, diff[RY][2] = {};

    #pragma unroll
    for (int k = 0; k < RY + 6; ++k) {
        int row = r0 + k, sb = row * S_STR, sz = row & 2;
        ull p[9];
        float v[10];
        #pragma unroll
        for (int m = 0; m < 5; ++m) {
            p[2 * m] = *reinterpret_cast<const ull*>(&tile[sb + ((c0 + 2 * m) ^ sz)]);
            f2unpack(p[2 * m], v[2 * m], v[2 * m + 1]);
        }
        #pragma unroll
        for (int m = 0; m < 4; ++m) p[2 * m + 1] = fpack(v[2 * m + 1], v[2 * m + 2]);

        // packed box row-sums: rs0 = (Sum v0..6, Sum v1..7), rs1 = (Sum v2..8, Sum v3..9)
        ull smid = f2add(f2add(f2add(p[2], p[3]), f2add(p[4], p[5])), p[6]);
        ull rs0  = f2add(smid, f2add(p[0], p[1]));
        ull rs1  = f2add(smid, f2add(p[7], p[8]));

        #pragma unroll
        for (int r = 0; r < RY; ++r) {
            const int i = k - r;            // tap row
            if (0 <= i && i <= 6) {
                mean[r][0] = f2add(mean[r][0], rs0);
                mean[r][1] = f2add(mean[r][1], rs1);
                #pragma unroll
                for (int j = 0; j < 7; ++j) {
                    ull w2 = sw2[i * 7 + j];            // (w/2, w/2) broadcast
                    ull t0 = f2add(p[j],     nxc[r][0]);
                    ull t1 = f2add(p[j + 2], nxc[r][1]);
                    // relu(t) * w = (w/2) * (t + |t|), exact in fp32
                    diff[r][0] = f2fma(w2, f2add(t0, t0 & ABSM), diff[r][0]);
                    diff[r][1] = f2fma(w2, f2add(t1, t1 & ABSM), diff[r][1]);
                }
            }
        }
    }

    // Epilogue: avg/diff/mask stores (float4) + local ||mask||^2
    float local = 0.f;
    #pragma unroll
    for (int r = 0; r < RY; ++r) {
        float m0, m1, m2, m3, d0, d1, d2, d3;
        f2unpack(mean[r][0], m0, m1);
        f2unpack(mean[r][1], m2, m3);
        f2unpack(diff[r][0], d0, d1);
        f2unpack(diff[r][1], d2, d3);
        float a0 = __expf(m0 * (-1.f / 49.f));
        float a1 = __expf(m1 * (-1.f / 49.f));
        float a2 = __expf(m2 * (-1.f / 49.f));
        float a3 = __expf(m3 * (-1.f / 49.f));
        float k0 = fmaf(B_W, d0, A_W * a0);
        float k1 = fmaf(B_W, d1, A_W * a1);
        float k2 = fmaf(B_W, d2, A_W * a2);
        float k3 = fmaf(B_W, d3, A_W * a3);
        local += k0 * k0 + k1 * k1;
        local += k2 * k2 + k3 * k3;
        size_t o = (size_t)b * NPIX + (size_t)(by + r0 + r) * IMG + (bx + c0);
        *reinterpret_cast<float4*>(&avg_out[o])  = make_float4(a0, a1, a2, a3);
        *reinterpret_cast<float4*>(&diff_out[o]) = make_float4(d0, d1, d2, d3);
        *reinterpret_cast<float4*>(&g_mask[o])   = make_float4(k0, k1, k2, k3);
    }

    // Block reduction -> one double atomic per block
    #pragma unroll
    for (int s = 16; s > 0; s >>= 1)
        local += __shfl_down_sync(0xffffffffu, local, s);
    const int lane = tid & 31, warp = tid >> 5;
    if (lane == 0) red[warp] = local;
    __syncthreads();
    if (warp == 0) {
        float v2 = (lane < 8) ? red[lane] : 0.f;
        #pragma unroll
        for (int s = 4; s > 0; s >>= 1)
            v2 += __shfl_down_sync(0xffffffffu, v2, s);
        if (lane == 0) atomicAdd(&g_sum, (double)v2);
    }
}

__global__ __launch_bounds__(256)
void threshold_kernel(const float* __restrict__ x, float* __restrict__ out, int n4)
{
    int i = blockIdx.x * blockDim.x + threadIdx.x;
    if (i >= n4) return;
    const float inv = g_inv;
    float4 xv = ((const float4*)x)[i];
    float4 mv = ((const float4*)g_mask)[i];
    float4 o;
    o.x = xv.x > mv.x * inv ? xv.x : 0.f;
    o.y = xv.y > mv.y * inv ? xv.y : 0.f;
    o.z = xv.z > mv.z * inv ? xv.z : 0.f;
    o.w = xv.w > mv.w * inv ? xv.w : 0.f;
    ((float4*)out)[i] = o;
}

extern "C" void kernel_launch(void* const* d_in, const int* in_sizes, int n_in,
                              void* d_out, int out_size)
{
    const float* x = (const float*)d_in[0];
    const float* w = (const float*)d_in[1];
    float* out = (float*)d_out;

    const int N     = in_sizes[0];          // 64*512*512
    const int batch = N / NPIX;             // 64

    float* avg_ptr;
    float* diff_ptr;
    if (out_size >= 3 * N) {                // verified layout: (out, avg, diff)
        avg_ptr  = out + N;
        diff_ptr = out + 2 * N;
    } else {
        void* pa = nullptr; void* pd = nullptr;
        cudaGetSymbolAddress(&pa, g_scr_a);
        cudaGetSymbolAddress(&pd, g_scr_d);
        avg_ptr  = (float*)pa;
        diff_ptr = (float*)pd;
    }

    zero_kernel<<<1, 1>>>();

    dim3 grid(IMG / TILE_W, IMG / TILE_H, batch);
    dim3 block(TXD, TYD);
    stencil_kernel<<<grid, block>>>(x, w, avg_ptr, diff_ptr);

    norm_kernel<<<1, 1>>>();

    const int n4 = N / 4;
    threshold_kernel<<<(n4 + 255) / 256, 256>>>(x, out, n4);
}